// round 15
// baseline (speedup 1.0000x reference)
#include <cuda_runtime.h>
#include <math.h>

#define BATCH 32
#define NROI 1000
#define NCLS 81
#define MAXI 100
#define NTOT (BATCH * NROI)
#define BPI 8                   // blocks per image
#define RPB 125                 // ROIs per block (8*125 = 1000, no tail)
#define BT 1024
#define FULL 0xffffffffu

// compacted per-image lists + tickets (zero-init; reset by epilogue each run)
__device__ float4 g_cbox[NTOT];
__device__ float4 g_cmeta[NTOT];   // {score, cls, origidx, 0}
__device__ int    g_cnt[BATCH];
__device__ int    g_done[BATCH];

struct Epi {
    float4 box[NROI];            // 16 KB
    float  score[NROI];          // 4 KB
    short  idx[NROI];
    short  cls[NROI];
    short  perm[NROI];
    short  sortd[NROI];
    unsigned char kp[NROI];
    int    ccount[NCLS];
    int    cstart[NCLS];
    int    ccur[NCLS];
    float  k_score[NROI];
    short  k_idx[NROI];
    short  k_ent[NROI];
    float  outbuf[MAXI * 6];
};

union SmemU {
    float tile[RPB * NCLS + 4];  // 40.5 KB phase-1 tile
    Epi   ep;                    // ~38.5 KB epilogue state
};

__global__ __launch_bounds__(BT, 2)
void det_kernel(const float* __restrict__ rois,
                const float* __restrict__ probs,
                const float* __restrict__ bbox,
                const float* __restrict__ std_dev,
                float* __restrict__ out)
{
    __shared__ SmemU u;
    __shared__ int s_wsum[32];
    __shared__ int s_K;
    __shared__ int s_last;

    const int img = blockIdx.x / BPI;
    const int sub = blockIdx.x - img * BPI;
    const int t   = threadIdx.x;
    const int wid = t >> 5;
    const int lane = t & 31;

    // ================= Phase 1: tile load + argmax + compact =================
    {
        const size_t s0 = ((size_t)img * NROI + sub * RPB) * NCLS;
        const int sh  = (int)(s0 & 3);
        const int NEL = RPB * NCLS;                 // 10125
        const int h   = (4 - sh) & 3;

        if (t < h) u.tile[sh + t] = probs[s0 + t];
        const int nvec = (NEL - h) >> 2;            // ~2531
        const float4* gp = (const float4*)(probs + s0 + h);
        float4* spv = (float4*)(u.tile + sh + h);
        // fixed 3 predicated independent LDG.128s per thread
        const int i0 = t, i1 = t + BT, i2 = t + 2 * BT;
        const bool p0 = i0 < nvec, p1 = i1 < nvec, p2 = i2 < nvec;
        float4 a0, a1, a2;
        if (p0) a0 = gp[i0];
        if (p1) a1 = gp[i1];
        if (p2) a2 = gp[i2];
        if (p0) spv[i0] = a0;
        if (p1) spv[i1] = a1;
        if (p2) spv[i2] = a2;
        const int tl = NEL - h - 4 * nvec;
        if (t < tl) { int e = h + 4 * nvec + t; u.tile[sh + e] = probs[s0 + e]; }
        __syncthreads();

        if (t < RPB) {
            const float* row = u.tile + sh + t * NCLS;   // stride 81: conflict-free
            float b0 = row[0]; int c0 = 0;
            float b1 = row[1]; int c1 = 1;
            float b2 = row[2]; int c2 = 2;
            #pragma unroll 13
            for (int c = 3; c < 81; c += 3) {
                float v0 = row[c];
                float v1 = row[c + 1];
                float v2 = row[c + 2];
                if (v0 > b0) { b0 = v0; c0 = c; }
                if (v1 > b1) { b1 = v1; c1 = c + 1; }
                if (v2 > b2) { b2 = v2; c2 = c + 2; }
            }
            float best = b0; int bi = c0;
            if (b1 > best || (b1 == best && c1 < bi)) { best = b1; bi = c1; }
            if (b2 > best || (b2 == best && c2 < bi)) { best = b2; bi = c2; }

            if (bi > 0 && best >= 0.7f) {
                const int r = sub * RPB + t;
                const size_t gri = (size_t)img * NROI + r;
                const float4 sd = *(const float4*)std_dev;
                const float4 dv = *(const float4*)(bbox + (gri * NCLS + bi) * 4);
                const float4 ro = *(const float4*)(rois + gri * 4);

                float d0 = dv.x * sd.x, d1 = dv.y * sd.y, d2 = dv.z * sd.z, d3 = dv.w * sd.w;
                float hh = ro.z - ro.x;
                float ww = ro.w - ro.y;
                float cy = ro.x + 0.5f * hh + d0 * hh;
                float cx = ro.y + 0.5f * ww + d1 * ww;
                hh *= expf(d2);
                ww *= expf(d3);
                float ny1 = cy - 0.5f * hh;
                float nx1 = cx - 0.5f * ww;
                float ny2 = ny1 + hh;
                float nx2 = nx1 + ww;
                ny1 = fminf(fmaxf(ny1, 0.0f), 1.0f);
                nx1 = fminf(fmaxf(nx1, 0.0f), 1.0f);
                ny2 = fminf(fmaxf(ny2, 0.0f), 1.0f);
                nx2 = fminf(fmaxf(nx2, 0.0f), 1.0f);

                int pos = atomicAdd(&g_cnt[img], 1);
                if (pos < NROI) {
                    g_cbox[img * NROI + pos]  = make_float4(ny1, nx1, ny2, nx2);
                    g_cmeta[img * NROI + pos] = make_float4(best, (float)bi, (float)r, 0.0f);
                }
            }
        }
    }

    // ================= Ticket: last block of image runs epilogue ==============
    __syncthreads();
    if (t == 0) {
        __threadfence();
        int tick = atomicAdd(&g_done[img], 1);
        s_last = (tick == BPI - 1) ? 1 : 0;
    }
    __syncthreads();
    if (!s_last) return;
    __threadfence();   // acquire: all blocks' writes visible

    // ================= Epilogue (R14 minimal-chain, 1024 threads) =============
    Epi& ep = u.ep;
    const int base = img * NROI;
    const int M = min(g_cnt[img], NROI);

    if (t < NCLS) { ep.ccount[t] = 0; ep.ccur[t] = 0; }
    for (int o = t; o < MAXI * 6; o += BT) ep.outbuf[o] = 0.0f;
    __syncthreads();   // union transition: tile reads done before ep writes land

    // ---- load entries (L2-warm), count classes ----
    int mycls = -1;
    if (t < M) {
        float4 m  = g_cmeta[base + t];
        float4 bx = g_cbox[base + t];
        ep.score[t] = m.x;
        ep.cls[t]   = (short)m.y;
        ep.idx[t]   = (short)m.z;
        ep.box[t]   = bx;
        mycls = (int)m.y;
    }
    __syncthreads();
    if (mycls >= 0) atomicAdd(&ep.ccount[mycls], 1);
    __syncthreads();

    // ---- warp0 shfl-scan of 81 class counts -> cstart ----
    if (wid == 0) {
        const int cA = lane, cB = lane + 32, cC = lane + 64;
        int v0 = ep.ccount[cA];
        int v1 = (cB < NCLS) ? ep.ccount[cB] : 0;
        int v2 = (cC < NCLS) ? ep.ccount[cC] : 0;
        int i0 = v0, i1 = v1, i2 = v2;
        #pragma unroll
        for (int off = 1; off < 32; off <<= 1) {
            int n0 = __shfl_up_sync(FULL, i0, off);
            int n1 = __shfl_up_sync(FULL, i1, off);
            int n2 = __shfl_up_sync(FULL, i2, off);
            if (lane >= off) { i0 += n0; i1 += n1; i2 += n2; }
        }
        const int tot0 = __shfl_sync(FULL, i0, 31);
        const int tot1 = __shfl_sync(FULL, i1, 31);
        ep.cstart[cA] = i0 - v0;
        if (cB < NCLS) ep.cstart[cB] = tot0 + i1 - v1;
        if (cC < NCLS) ep.cstart[cC] = tot0 + tot1 + i2 - v2;
    }
    __syncthreads();

    // ---- scatter entries into class regions (unstable) ----
    if (mycls >= 0) {
        int p = ep.cstart[mycls] + atomicAdd(&ep.ccur[mycls], 1);
        ep.perm[p] = (short)t;
    }
    __syncthreads();

    // ---- warp-per-class sort + greedy NMS ----
    for (int c = wid; c < NCLS; c += 32) {
        const int cs = ep.cstart[c];
        const int n  = ep.ccount[c];
        if (n <= 0) continue;
        if (n <= 32) {
            const bool v = (lane < n);
            int e = 0; float sc = -1.0f, idf = 1e9f;
            float4 bb = make_float4(0.f, 0.f, 0.f, 0.f);
            if (v) {
                e = ep.perm[cs + lane];
                sc = ep.score[e]; idf = (float)ep.idx[e];
                bb = ep.box[e];
            }
            int rank = v ? 0 : 999;
            for (int m2 = 0; m2 < n; ++m2) {
                float s2 = __shfl_sync(FULL, sc,  m2);
                float i2 = __shfl_sync(FULL, idf, m2);
                if (v) rank += (s2 > sc) || (s2 == sc && i2 < idf);
            }
            int keep = v ? 1 : 0;
            float area = (bb.z - bb.x) * (bb.w - bb.y);
            for (int a = 0; a < n - 1; ++a) {
                unsigned am = __ballot_sync(FULL, rank == a);
                int src = __ffs(am) - 1;
                int ks  = __shfl_sync(FULL, keep, src);
                float sy1 = __shfl_sync(FULL, bb.x, src);
                float sx1 = __shfl_sync(FULL, bb.y, src);
                float sy2 = __shfl_sync(FULL, bb.z, src);
                float sx2 = __shfl_sync(FULL, bb.w, src);
                float sa  = __shfl_sync(FULL, area, src);
                if (ks && keep && rank > a) {
                    float ih = fmaxf(fminf(sy2, bb.z) - fmaxf(sy1, bb.x), 0.0f);
                    float iw = fmaxf(fminf(sx2, bb.w) - fmaxf(sx1, bb.y), 0.0f);
                    float inter = ih * iw;
                    float iou = inter / fmaxf(sa + area - inter, 1e-8f);
                    if (iou > 0.3f) keep = 0;
                }
            }
            if (v) { ep.sortd[cs + rank] = (short)e; ep.kp[cs + rank] = (unsigned char)keep; }
        } else {
            for (int p = lane; p < n; p += 32) {
                int e = ep.perm[cs + p];
                float sc = ep.score[e]; short id = ep.idx[e];
                int rank = 0;
                for (int j = 0; j < n; ++j) {
                    int ej = ep.perm[cs + j];
                    float sj = ep.score[ej];
                    rank += (sj > sc) || (sj == sc && ep.idx[ej] < id);
                }
                ep.sortd[cs + rank] = (short)e;
                ep.kp[cs + rank] = 1;
            }
            __syncwarp();
            for (int a = 0; a < n - 1; ++a) {
                if (!ep.kp[cs + a]) continue;
                int ea = ep.sortd[cs + a];
                float4 ba = ep.box[ea];
                float aa = (ba.z - ba.x) * (ba.w - ba.y);
                for (int q = a + 1 + lane; q < n; q += 32) {
                    if (!ep.kp[cs + q]) continue;
                    int eq = ep.sortd[cs + q];
                    float4 bq = ep.box[eq];
                    float ab = (bq.z - bq.x) * (bq.w - bq.y);
                    float ih = fmaxf(fminf(ba.z, bq.z) - fmaxf(ba.x, bq.x), 0.0f);
                    float iw = fmaxf(fminf(ba.w, bq.w) - fmaxf(ba.y, bq.y), 0.0f);
                    float inter = ih * iw;
                    float iou = inter / fmaxf(aa + ab - inter, 1e-8f);
                    if (iou > 0.3f) ep.kp[cs + q] = 0;
                }
                __syncwarp();
            }
        }
    }
    __syncthreads();

    // ---- compact kept entries (single ballot scan; M < 1024) ----
    int kflag = 0; int ke = -1;
    if (t < M && ep.kp[t]) { kflag = 1; ke = ep.sortd[t]; }
    {
        unsigned mask = __ballot_sync(FULL, kflag);
        if (lane == 0) s_wsum[wid] = __popc(mask);
        __syncthreads();
        if (wid == 0) {
            int v = s_wsum[lane];
            int inc = v;
            #pragma unroll
            for (int off = 1; off < 32; off <<= 1) {
                int nn = __shfl_up_sync(FULL, inc, off);
                if (lane >= off) inc += nn;
            }
            s_wsum[lane] = inc - v;
            if (lane == 31) s_K = inc;
        }
        __syncthreads();
        int slot = s_wsum[wid] + __popc(mask & ((1u << lane) - 1));
        if (kflag) {
            ep.k_score[slot] = ep.score[ke];
            ep.k_idx[slot]   = ep.idx[ke];
            ep.k_ent[slot]   = (short)ke;
        }
    }
    __syncthreads();
    const int K = s_K;

    // ---- rank kept globally (score desc, idx asc) == output slot ----
    if (t < K) {
        float sc = ep.k_score[t]; short id = ep.k_idx[t];
        int rank = 0;
        for (int j = 0; j < K; ++j) {
            float sj = ep.k_score[j];
            rank += (sj > sc) || (sj == sc && ep.k_idx[j] < id);
        }
        if (rank < MAXI) {
            int ee = ep.k_ent[t];
            float4 b4 = ep.box[ee];
            ep.outbuf[rank * 6 + 0] = b4.x;
            ep.outbuf[rank * 6 + 1] = b4.y;
            ep.outbuf[rank * 6 + 2] = b4.z;
            ep.outbuf[rank * 6 + 3] = b4.w;
            ep.outbuf[rank * 6 + 4] = (float)ep.cls[ee];
            ep.outbuf[rank * 6 + 5] = sc;
        }
    }
    __syncthreads();

    float* ob = out + (size_t)img * MAXI * 6;
    for (int o = t; o < MAXI * 6; o += BT) ob[o] = ep.outbuf[o];

    if (t == 0) { g_cnt[img] = 0; g_done[img] = 0; }   // reset for next replay
}

extern "C" void kernel_launch(void* const* d_in, const int* in_sizes, int n_in,
                              void* d_out, int out_size)
{
    const float* rois    = (const float*)d_in[0];
    const float* probs   = (const float*)d_in[1];
    const float* bbox    = (const float*)d_in[2];
    const float* std_dev = (const float*)d_in[3];
    float* out = (float*)d_out;
    det_kernel<<<BATCH * BPI, BT>>>(rois, probs, bbox, std_dev, out);
}